// round 12
// baseline (speedup 1.0000x reference)
#include <cuda_runtime.h>
#include <cuda_fp16.h>

// MVF_Dyn: trilinear-upsampled motion-field warp of a 2-channel 3D image.
//   image:       [1,1,48,256,256,2] f32
//   mvf_kernels: [1,4,3,48,128,128] f32
//   out:         [1,5,48,256,256,2] f32  (phase 0 = copy of image, 1..4 warped)
//
// Round-12: prep traffic cut. (1) z-chunked prep: one block packs 12 z-rows
// for one y, double-buffering image rows in smem -> each image row read
// ~1.08x instead of 2x. (2) phase-0 copy moved into the warp kernel as a 5th
// grid.z slice (coalesced, ~2% extra wavefronts; fills the warp kernel's idle
// DRAM capacity). Warp gather path is byte-identical to round 11.

namespace {

constexpr int Dv = 48, Hv = 256, Wv = 256;
constexpr int HM = 128, WM = 128;
constexpr int PH = 4;
constexpr int ZC = 12;  // z-rows packed per prep block (48 = 4 * 12)

// 48*256*256 * 16B = 50.3 MB scratch (z+x paired fp16).
__device__ uint4 g_pairs[Dv * Hv * Wv];

__device__ __forceinline__ unsigned pack_h2(float a, float b) {
  __half2 h = __floats2half2_rn(a, b);
  return *reinterpret_cast<unsigned*>(&h);
}

// Builds g_pairs (fp16, z+x paired). Block = (y, z-chunk); 128 threads,
// thread t owns the x-pair (2t, 2t+1). Image rows stream through a smem
// double buffer so each row is loaded ~once.
__global__ void __launch_bounds__(128)
prep_kernel(const float4* __restrict__ img4) {
  const int y = blockIdx.x;
  const int z0 = blockIdx.y * ZC;
  const int t = threadIdx.x;           // 0..127 -> x-pair
  __shared__ float4 buf[2][WM + 1];    // [parity][x-pair], +1 zero pad

  // Preload row z0.
  float4 vc = img4[(z0 * Hv + y) * (Wv / 2) + t];
  buf[0][t] = vc;
  if (t == 0) {
    buf[0][WM] = make_float4(0.f, 0.f, 0.f, 0.f);
    buf[1][WM] = make_float4(0.f, 0.f, 0.f, 0.f);
  }
  __syncthreads();

  for (int i = 0; i < ZC; i++) {
    const int z = z0 + i;
    const int zn = z + 1;
    float4 vn = make_float4(0.f, 0.f, 0.f, 0.f);
    if (zn < Dv) vn = img4[(zn * Hv + y) * (Wv / 2) + t];
    buf[(i + 1) & 1][t] = vn;
    __syncthreads();                       // next-row smem visible

    const float4 n0 = buf[i & 1][t + 1];       // row z,  px (2t+2, 2t+3)
    const float4 n1 = buf[(i + 1) & 1][t + 1]; // row z+1, same

    uint4 qa;  // entry x=2t:   (z,2t)(z,2t+1)(z+1,2t)(z+1,2t+1)
    qa.x = pack_h2(vc.x, vc.y);
    qa.y = pack_h2(vc.z, vc.w);
    qa.z = pack_h2(vn.x, vn.y);
    qa.w = pack_h2(vn.z, vn.w);
    uint4 qb;  // entry x=2t+1: (z,2t+1)(z,2t+2)(z+1,2t+1)(z+1,2t+2)
    qb.x = qa.y;
    qb.y = pack_h2(n0.x, n0.y);
    qb.z = qa.w;
    qb.w = pack_h2(n1.x, n1.y);

    const int ebase = (z * Hv + y) * Wv + 2 * t;
    g_pairs[ebase] = qa;
    g_pairs[ebase + 1] = qb;

    vc = vn;
    __syncthreads();                       // all reads of buf[i&1] done
  }
}

__device__ __forceinline__ float2 h2f(unsigned u) {
  return __half22float2(*reinterpret_cast<__half2*>(&u));
}

// Address + weight setup for one trilinear sample (zero-padding semantics).
// OOB taps -> zero weight on clamped (always-valid) indices; no branches.
struct Ctx {
  int i0, i1;                       // gather indices, rows y0 / y0+1
  float wa, wb, za, zb, wy0, wy1;   // x-half, z-half, y-row weights
};

__device__ __forceinline__ Ctx make_ctx(float z, float y, float x) {
  Ctx c;
  const int z0 = __float2int_rd(z);
  const int y0 = __float2int_rd(y);
  const int x0 = __float2int_rd(x);
  const float wz = z - (float)z0, wy = y - (float)y0, wx = x - (float)x0;

  const bool xin = (unsigned)x0 < (unsigned)Wv;
  const int xc = xin ? x0 : 0;
  c.wa = xin ? (1.f - wx) : ((x0 == -1) ? wx : 0.f);  // x0 half
  c.wb = xin ? wx : 0.f;                              // x0+1 half

  const bool zin = (unsigned)z0 < (unsigned)Dv;
  const int zc = zin ? z0 : 0;
  c.za = zin ? (1.f - wz) : ((z0 == -1) ? wz : 0.f);  // z lo half
  c.zb = zin ? wz : 0.f;                              // z hi half

  const int y0c = min(max(y0, 0), Hv - 1);
  const int y1c = min(max(y0 + 1, 0), Hv - 1);
  c.wy0 = ((unsigned)y0 < (unsigned)Hv) ? (1.f - wy) : 0.f;
  c.wy1 = ((unsigned)(y0 + 1) < (unsigned)Hv) ? wy : 0.f;

  const int base = zc * (Hv * Wv) + xc;               // 32-bit index
  c.i0 = base + y0c * Wv;
  c.i1 = base + y1c * Wv;
  return c;
}

__device__ __forceinline__ float2 combine(const Ctx& c, uint4 qa, uint4 qb) {
  float2 r;
  {
    const float2 a0 = h2f(qa.x), a1 = h2f(qa.y), b0 = h2f(qa.z), b1 = h2f(qa.w);
    const float t0x = fmaf(c.za, a0.x, c.zb * b0.x), t0y = fmaf(c.za, a0.y, c.zb * b0.y);
    const float t1x = fmaf(c.za, a1.x, c.zb * b1.x), t1y = fmaf(c.za, a1.y, c.zb * b1.y);
    r.x = c.wy0 * fmaf(c.wa, t0x, c.wb * t1x);
    r.y = c.wy0 * fmaf(c.wa, t0y, c.wb * t1y);
  }
  {
    const float2 a0 = h2f(qb.x), a1 = h2f(qb.y), b0 = h2f(qb.z), b1 = h2f(qb.w);
    const float t0x = fmaf(c.za, a0.x, c.zb * b0.x), t0y = fmaf(c.za, a0.y, c.zb * b0.y);
    const float t1x = fmaf(c.za, a1.x, c.zb * b1.x), t1y = fmaf(c.za, a1.y, c.zb * b1.y);
    r.x = fmaf(c.wy1, fmaf(c.wa, t0x, c.wb * t1x), r.x);
    r.y = fmaf(c.wy1, fmaf(c.wa, t0y, c.wb * t1y), r.y);
  }
  return r;
}

// grid.z slices 0..3: warp phases 1..4 (2 rows per 128-thread block,
// 4 samples/thread, 8 batched LDG.128s). Slice 4: phase-0 copy blocks.
// jax.image.resize 'trilinear' 2x (half-pixel, edge-renormalized):
//   even out idx 2j   -> taps (j-1, j)  weights (0.25, 0.75), clamp at edges
//   odd  out idx 2j+1 -> taps (j, j+1)  weights (0.75, 0.25), clamp at edges
// Depth is identity.
__global__ void __launch_bounds__(128, 8)
warp_kernel(const float* __restrict__ mvf,     // [4][3][48][128][128]
            const float4* __restrict__ img4,   // image as float4 (w pairs)
            float4* __restrict__ out) {        // output as float4 (w pairs)
  const int h0 = blockIdx.x * 2;
  const int d = blockIdx.y;
  const int p = blockIdx.z;
  const int k = threadIdx.x;      // 0..127 w-pair

  if (p == PH) {  // phase-0 verbatim copy (block-uniform branch)
    const int idx = (d * Hv + h0) * (Wv / 2) + k;
    const float4 a = __ldg(&img4[idx]);
    const float4 b = __ldg(&img4[idx + (Wv / 2)]);
    __stcs(&out[idx], a);
    __stcs(&out[idx + (Wv / 2)], b);
    return;
  }

  const int a = h0 >> 1;

  // Stage mvf source rows a-1, a, a+1 (clamped) for 3 channels.
  __shared__ float s[3][3][WM];
  {
    const int r0 = max(a - 1, 0), r1 = a, r2 = min(a + 1, HM - 1);
    const float* pl = mvf + ((size_t)(p * 3) * Dv + d) * (size_t)(HM * WM);
    const int plane = Dv * HM * WM;
#pragma unroll
    for (int c = 0; c < 3; c++) {
      const float* pc = pl + c * plane;
      s[c][0][k] = __ldg(pc + r0 * WM + k);
      s[c][1][k] = __ldg(pc + r1 * WM + k);
      s[c][2][k] = __ldg(pc + r2 * WM + k);
    }
  }
  __syncthreads();

  const int km1 = max(k - 1, 0);
  const int kp1 = min(k + 1, WM - 1);

  // mvf upsampled at (row h0 even/odd w) and (row h0+1 even/odd w).
  // row h0   (even h): y-taps (r0,r1) weights (0.25, 0.75)
  // row h0+1 (odd  h): y-taps (r1,r2) weights (0.75, 0.25)
  float mA[3], mB[3], mC[3], mD[3];
#pragma unroll
  for (int c = 0; c < 3; c++) {
    const float a0 = s[c][0][km1], b0 = s[c][0][k], c0 = s[c][0][kp1];
    const float a1 = s[c][1][km1], b1 = s[c][1][k], c1 = s[c][1][kp1];
    const float a2 = s[c][2][km1], b2 = s[c][2][k], c2 = s[c][2][kp1];
    const float e0 = fmaf(0.25f, a0, 0.75f * b0), o0 = fmaf(0.75f, b0, 0.25f * c0);
    const float e1 = fmaf(0.25f, a1, 0.75f * b1), o1 = fmaf(0.75f, b1, 0.25f * c1);
    const float e2 = fmaf(0.25f, a2, 0.75f * b2), o2 = fmaf(0.75f, b2, 0.25f * c2);
    mA[c] = fmaf(0.25f, e0, 0.75f * e1);  // row h0,   even w
    mB[c] = fmaf(0.25f, o0, 0.75f * o1);  // row h0,   odd  w
    mC[c] = fmaf(0.75f, e1, 0.25f * e2);  // row h0+1, even w
    mD[c] = fmaf(0.75f, o1, 0.25f * o2);  // row h0+1, odd  w
  }

  const float fd = (float)d;
  const float f0 = (float)h0, f1 = (float)(h0 + 1);
  const float xe = (float)(2 * k), xo = (float)(2 * k + 1);

  const Ctx cA = make_ctx(fd + mA[0], f0 + 2.f * mA[1], xe + 2.f * mA[2]);
  const Ctx cB = make_ctx(fd + mB[0], f0 + 2.f * mB[1], xo + 2.f * mB[2]);
  const Ctx cC = make_ctx(fd + mC[0], f1 + 2.f * mC[1], xe + 2.f * mC[2]);
  const Ctx cD = make_ctx(fd + mD[0], f1 + 2.f * mD[1], xo + 2.f * mD[2]);

  // All eight gathers in flight before any consumption.
  const uint4 qA0 = __ldg(&g_pairs[cA.i0]);
  const uint4 qA1 = __ldg(&g_pairs[cA.i1]);
  const uint4 qB0 = __ldg(&g_pairs[cB.i0]);
  const uint4 qB1 = __ldg(&g_pairs[cB.i1]);
  const uint4 qC0 = __ldg(&g_pairs[cC.i0]);
  const uint4 qC1 = __ldg(&g_pairs[cC.i1]);
  const uint4 qD0 = __ldg(&g_pairs[cD.i0]);
  const uint4 qD1 = __ldg(&g_pairs[cD.i1]);

  const float2 rA = combine(cA, qA0, qA1);
  const float2 rB = combine(cB, qB0, qB1);
  const float2 rC = combine(cC, qC0, qC1);
  const float2 rD = combine(cD, qD0, qD1);

  // 32-bit output index: max (5*48*256)*128 = 7.9M < 2^31.
  const int oidx = (((p + 1) * Dv + d) * Hv + h0) * (Wv / 2) + k;
  __stcs(&out[oidx], make_float4(rA.x, rA.y, rB.x, rB.y));
  __stcs(&out[oidx + (Wv / 2)], make_float4(rC.x, rC.y, rD.x, rD.y));
}

}  // namespace

extern "C" void kernel_launch(void* const* d_in, const int* in_sizes, int n_in,
                              void* d_out, int out_size) {
  const float* image = (const float*)d_in[0];
  const float* mvf   = (const float*)d_in[1];
  // Defensive: identify inputs by size (image has 48*256*256*2 = 6291456 elems).
  if (n_in >= 2 && in_sizes[0] != Dv * Hv * Wv * 2) {
    const float* t = image; image = mvf; mvf = t;
  }

  // Build z+x paired fp16 layout (z-chunked, image read ~once).
  dim3 pgrid(Hv, Dv / ZC);
  prep_kernel<<<pgrid, 128>>>((const float4*)image);

  // Slices 0..3: warp phases 1..4. Slice 4: phase-0 copy.
  dim3 grid(Hv / 2, Dv, PH + 1);
  warp_kernel<<<grid, 128>>>(mvf, (const float4*)image, (float4*)d_out);
}

// round 15
// speedup vs baseline: 1.0168x; 1.0168x over previous
#include <cuda_runtime.h>
#include <cuda_fp16.h>

// MVF_Dyn: trilinear-upsampled motion-field warp of a 2-channel 3D image.
//   image:       [1,1,48,256,256,2] f32
//   mvf_kernels: [1,4,3,48,128,128] f32
//   out:         [1,5,48,256,256,2] f32  (phase 0 = copy of image, 1..4 warped)
//
// Round-15: phase-0 copy folded into the z-chunked prep kernel, which already
// streams every image row through registers -> the copy costs zero extra
// reads (just 25MB of coalesced streaming stores on top of the 13.2us r12
// prep). Warp kernel is byte-identical to round 11 (measured 89.5us).

namespace {

constexpr int Dv = 48, Hv = 256, Wv = 256;
constexpr int HM = 128, WM = 128;
constexpr int PH = 4;
constexpr int ZC = 12;  // z-rows packed per prep block (48 = 4 * 12)

// 48*256*256 * 16B = 50.3 MB scratch (z+x paired fp16).
__device__ uint4 g_pairs[Dv * Hv * Wv];

__device__ __forceinline__ unsigned pack_h2(float a, float b) {
  __half2 h = __floats2half2_rn(a, b);
  return *reinterpret_cast<unsigned*>(&h);
}

// Builds g_pairs (fp16, z+x paired) AND writes the phase-0 fp32 copy.
// Block = (y, z-chunk); 128 threads, thread t owns the x-pair (2t, 2t+1).
// Image rows stream through a smem double buffer so each row is loaded ~once;
// the same register data feeds the out0 copy for free.
__global__ void __launch_bounds__(128)
prep_kernel(const float4* __restrict__ img4, float4* __restrict__ out04) {
  const int y = blockIdx.x;
  const int z0 = blockIdx.y * ZC;
  const int t = threadIdx.x;           // 0..127 -> x-pair
  __shared__ float4 buf[2][WM + 1];    // [parity][x-pair], +1 zero pad

  // Preload row z0.
  float4 vc = img4[(z0 * Hv + y) * (Wv / 2) + t];
  buf[0][t] = vc;
  if (t == 0) {
    buf[0][WM] = make_float4(0.f, 0.f, 0.f, 0.f);
    buf[1][WM] = make_float4(0.f, 0.f, 0.f, 0.f);
  }
  __syncthreads();

  for (int i = 0; i < ZC; i++) {
    const int z = z0 + i;
    const int zn = z + 1;
    float4 vn = make_float4(0.f, 0.f, 0.f, 0.f);
    if (zn < Dv) vn = img4[(zn * Hv + y) * (Wv / 2) + t];
    buf[(i + 1) & 1][t] = vn;
    __syncthreads();                       // next-row smem visible

    const float4 n0 = buf[i & 1][t + 1];       // row z,   px (2t+2, 2t+3)
    const float4 n1 = buf[(i + 1) & 1][t + 1]; // row z+1, same

    uint4 qa;  // entry x=2t:   (z,2t)(z,2t+1)(z+1,2t)(z+1,2t+1)
    qa.x = pack_h2(vc.x, vc.y);
    qa.y = pack_h2(vc.z, vc.w);
    qa.z = pack_h2(vn.x, vn.y);
    qa.w = pack_h2(vn.z, vn.w);
    uint4 qb;  // entry x=2t+1: (z,2t+1)(z,2t+2)(z+1,2t+1)(z+1,2t+2)
    qb.x = qa.y;
    qb.y = pack_h2(n0.x, n0.y);
    qb.z = qa.w;
    qb.w = pack_h2(n1.x, n1.y);

    const int ebase = (z * Hv + y) * Wv + 2 * t;
    g_pairs[ebase] = qa;
    g_pairs[ebase + 1] = qb;
    __stcs(&out04[(z * Hv + y) * (Wv / 2) + t], vc);  // phase-0 copy, free read

    vc = vn;
    __syncthreads();                       // all reads of buf[i&1] done
  }
}

__device__ __forceinline__ float2 h2f(unsigned u) {
  return __half22float2(*reinterpret_cast<__half2*>(&u));
}

// Address + weight setup for one trilinear sample (zero-padding semantics).
// OOB taps -> zero weight on clamped (always-valid) indices; no branches.
struct Ctx {
  int i0, i1;                       // gather indices, rows y0 / y0+1
  float wa, wb, za, zb, wy0, wy1;   // x-half, z-half, y-row weights
};

__device__ __forceinline__ Ctx make_ctx(float z, float y, float x) {
  Ctx c;
  const int z0 = __float2int_rd(z);
  const int y0 = __float2int_rd(y);
  const int x0 = __float2int_rd(x);
  const float wz = z - (float)z0, wy = y - (float)y0, wx = x - (float)x0;

  const bool xin = (unsigned)x0 < (unsigned)Wv;
  const int xc = xin ? x0 : 0;
  c.wa = xin ? (1.f - wx) : ((x0 == -1) ? wx : 0.f);  // x0 half
  c.wb = xin ? wx : 0.f;                              // x0+1 half

  const bool zin = (unsigned)z0 < (unsigned)Dv;
  const int zc = zin ? z0 : 0;
  c.za = zin ? (1.f - wz) : ((z0 == -1) ? wz : 0.f);  // z lo half
  c.zb = zin ? wz : 0.f;                              // z hi half

  const int y0c = min(max(y0, 0), Hv - 1);
  const int y1c = min(max(y0 + 1, 0), Hv - 1);
  c.wy0 = ((unsigned)y0 < (unsigned)Hv) ? (1.f - wy) : 0.f;
  c.wy1 = ((unsigned)(y0 + 1) < (unsigned)Hv) ? wy : 0.f;

  const int base = zc * (Hv * Wv) + xc;               // 32-bit index
  c.i0 = base + y0c * Wv;
  c.i1 = base + y1c * Wv;
  return c;
}

__device__ __forceinline__ float2 combine(const Ctx& c, uint4 qa, uint4 qb) {
  float2 r;
  {
    const float2 a0 = h2f(qa.x), a1 = h2f(qa.y), b0 = h2f(qa.z), b1 = h2f(qa.w);
    const float t0x = fmaf(c.za, a0.x, c.zb * b0.x), t0y = fmaf(c.za, a0.y, c.zb * b0.y);
    const float t1x = fmaf(c.za, a1.x, c.zb * b1.x), t1y = fmaf(c.za, a1.y, c.zb * b1.y);
    r.x = c.wy0 * fmaf(c.wa, t0x, c.wb * t1x);
    r.y = c.wy0 * fmaf(c.wa, t0y, c.wb * t1y);
  }
  {
    const float2 a0 = h2f(qb.x), a1 = h2f(qb.y), b0 = h2f(qb.z), b1 = h2f(qb.w);
    const float t0x = fmaf(c.za, a0.x, c.zb * b0.x), t0y = fmaf(c.za, a0.y, c.zb * b0.y);
    const float t1x = fmaf(c.za, a1.x, c.zb * b1.x), t1y = fmaf(c.za, a1.y, c.zb * b1.y);
    r.x = fmaf(c.wy1, fmaf(c.wa, t0x, c.wb * t1x), r.x);
    r.y = fmaf(c.wy1, fmaf(c.wa, t0y, c.wb * t1y), r.y);
  }
  return r;
}

// Block: 128 threads = 2 output rows (h0, h0+1) of one (d, p).
// Thread k owns w-pair k on BOTH rows: 4 samples, 8 LDG.128s batched.
// jax.image.resize 'trilinear' 2x (half-pixel, edge-renormalized):
//   even out idx 2j   -> taps (j-1, j)  weights (0.25, 0.75), clamp at edges
//   odd  out idx 2j+1 -> taps (j, j+1)  weights (0.75, 0.25), clamp at edges
// Depth is identity.
__global__ void __launch_bounds__(128, 8)
warp_kernel(const float* __restrict__ mvf,    // [4][3][48][128][128]
            float4* __restrict__ out) {       // output as float4 (w pairs)
  const int h0 = blockIdx.x * 2;
  const int d = blockIdx.y;
  const int p = blockIdx.z;
  const int k = threadIdx.x;      // 0..127 w-pair
  const int a = h0 >> 1;

  // Stage mvf source rows a-1, a, a+1 (clamped) for 3 channels.
  __shared__ float s[3][3][WM];
  {
    const int r0 = max(a - 1, 0), r1 = a, r2 = min(a + 1, HM - 1);
    const float* pl = mvf + ((size_t)(p * 3) * Dv + d) * (size_t)(HM * WM);
    const int plane = Dv * HM * WM;
#pragma unroll
    for (int c = 0; c < 3; c++) {
      const float* pc = pl + c * plane;
      s[c][0][k] = __ldg(pc + r0 * WM + k);
      s[c][1][k] = __ldg(pc + r1 * WM + k);
      s[c][2][k] = __ldg(pc + r2 * WM + k);
    }
  }
  __syncthreads();

  const int km1 = max(k - 1, 0);
  const int kp1 = min(k + 1, WM - 1);

  // mvf upsampled at (row h0 even/odd w) and (row h0+1 even/odd w).
  // row h0   (even h): y-taps (r0,r1) weights (0.25, 0.75)
  // row h0+1 (odd  h): y-taps (r1,r2) weights (0.75, 0.25)
  float mA[3], mB[3], mC[3], mD[3];
#pragma unroll
  for (int c = 0; c < 3; c++) {
    const float a0 = s[c][0][km1], b0 = s[c][0][k], c0 = s[c][0][kp1];
    const float a1 = s[c][1][km1], b1 = s[c][1][k], c1 = s[c][1][kp1];
    const float a2 = s[c][2][km1], b2 = s[c][2][k], c2 = s[c][2][kp1];
    const float e0 = fmaf(0.25f, a0, 0.75f * b0), o0 = fmaf(0.75f, b0, 0.25f * c0);
    const float e1 = fmaf(0.25f, a1, 0.75f * b1), o1 = fmaf(0.75f, b1, 0.25f * c1);
    const float e2 = fmaf(0.25f, a2, 0.75f * b2), o2 = fmaf(0.75f, b2, 0.25f * c2);
    mA[c] = fmaf(0.25f, e0, 0.75f * e1);  // row h0,   even w
    mB[c] = fmaf(0.25f, o0, 0.75f * o1);  // row h0,   odd  w
    mC[c] = fmaf(0.75f, e1, 0.25f * e2);  // row h0+1, even w
    mD[c] = fmaf(0.75f, o1, 0.25f * o2);  // row h0+1, odd  w
  }

  const float fd = (float)d;
  const float f0 = (float)h0, f1 = (float)(h0 + 1);
  const float xe = (float)(2 * k), xo = (float)(2 * k + 1);

  const Ctx cA = make_ctx(fd + mA[0], f0 + 2.f * mA[1], xe + 2.f * mA[2]);
  const Ctx cB = make_ctx(fd + mB[0], f0 + 2.f * mB[1], xo + 2.f * mB[2]);
  const Ctx cC = make_ctx(fd + mC[0], f1 + 2.f * mC[1], xe + 2.f * mC[2]);
  const Ctx cD = make_ctx(fd + mD[0], f1 + 2.f * mD[1], xo + 2.f * mD[2]);

  // All eight gathers in flight before any consumption.
  const uint4 qA0 = __ldg(&g_pairs[cA.i0]);
  const uint4 qA1 = __ldg(&g_pairs[cA.i1]);
  const uint4 qB0 = __ldg(&g_pairs[cB.i0]);
  const uint4 qB1 = __ldg(&g_pairs[cB.i1]);
  const uint4 qC0 = __ldg(&g_pairs[cC.i0]);
  const uint4 qC1 = __ldg(&g_pairs[cC.i1]);
  const uint4 qD0 = __ldg(&g_pairs[cD.i0]);
  const uint4 qD1 = __ldg(&g_pairs[cD.i1]);

  const float2 rA = combine(cA, qA0, qA1);
  const float2 rB = combine(cB, qB0, qB1);
  const float2 rC = combine(cC, qC0, qC1);
  const float2 rD = combine(cD, qD0, qD1);

  // 32-bit output index: max (5*48*256)*128 = 7.9M < 2^31.
  const int oidx = (((p + 1) * Dv + d) * Hv + h0) * (Wv / 2) + k;
  __stcs(&out[oidx], make_float4(rA.x, rA.y, rB.x, rB.y));
  __stcs(&out[oidx + (Wv / 2)], make_float4(rC.x, rC.y, rD.x, rD.y));
}

}  // namespace

extern "C" void kernel_launch(void* const* d_in, const int* in_sizes, int n_in,
                              void* d_out, int out_size) {
  const float* image = (const float*)d_in[0];
  const float* mvf   = (const float*)d_in[1];
  // Defensive: identify inputs by size (image has 48*256*256*2 = 6291456 elems).
  if (n_in >= 2 && in_sizes[0] != Dv * Hv * Wv * 2) {
    const float* t = image; image = mvf; mvf = t;
  }

  // Build z+x paired fp16 layout + phase-0 copy (z-chunked, image read ~once).
  dim3 pgrid(Hv, Dv / ZC);
  prep_kernel<<<pgrid, 128>>>((const float4*)image, (float4*)d_out);

  // Phases 1..4: warp. 2 output rows per 128-thread block, 4 samples/thread.
  dim3 grid(Hv / 2, Dv, PH);
  warp_kernel<<<grid, 128>>>(mvf, (float4*)d_out);
}